// round 9
// baseline (speedup 1.0000x reference)
#include <cuda_runtime.h>
#include <math.h>

// Shapelet_66932770341112 on sm_103a
// B=16, C=8, T=512, L=24, STRIDE=2, N=64, M=245, EPS=1
// d(b,m,n,c) = (1/L) * sum_l |x[b,c,2m+l] - w[n,c,l]| * pcm[c,m]
// out[0 : B*N*C]       = exp(-(min_m |d|)^2)
// out[B*N*C : 2*B*N*C] = min_m d

#define BB 16
#define CC 8
#define TT 512
#define LL 24
#define NN 64
#define MM 245
#define NBLK 4             // n per block

// swizzle pair-index -> physical slot; breaks stride-2 LDS.64 bank conflicts
__device__ __forceinline__ int swz(int i) { return i + (i >> 3); }

__global__ __launch_bounds__(128)
void shapelet_kernel(const float* __restrict__ x,
                     const float* __restrict__ w,
                     const float* __restrict__ pcm,
                     float* __restrict__ out)
{
    __shared__ float2 xsm[304];            // swizzled x pairs: pair(t)=(x[2t],x[2t+1])
    __shared__ float4 wsm[NBLK][6];        // 4 shapelets' weights (raw)
    __shared__ float2 dsm[NBLK][128];      // per-(n, m-pair) (dmin, min|d|)

    const int bc    = blockIdx.x;          // b*C + c
    const int b     = bc >> 3;
    const int c     = bc & 7;
    const int n0    = blockIdx.y * NBLK;
    const int tid   = threadIdx.x;         // 0..127 == m-pair index
    const int lane  = tid & 31;
    const int warp  = tid >> 5;            // 0..3

    // ---- x row: 256 float2 pairs (swizzled) + zero pad ----
    {
        const float2* xrow = (const float2*)(x + bc * TT);
        xsm[swz(tid)]       = xrow[tid];
        xsm[swz(tid + 128)] = xrow[tid + 128];
        if (tid < 11) xsm[swz(256 + tid)] = make_float2(0.f, 0.f);
    }
    // ---- 4 shapelets' weights for channel c (96 floats) ----
    if (tid < NBLK * LL) {
        const int j = tid / LL;
        const int l = tid % LL;
        ((float*)wsm)[j * LL + l] = w[((n0 + j) * CC + c) * LL + l];
    }
    __syncthreads();

    // ---- scalar register window: xw[i] = x[2*m0 + i], i=0..25 (covers m0, m0+1) ----
    const int m0 = 2 * tid;
    float xw[26];
#pragma unroll
    for (int k = 0; k < 13; ++k) {
        const float2 p = xsm[swz(m0 + k)];
        xw[2 * k]     = p.x;
        xw[2 * k + 1] = p.y;
    }

    const float INF = __int_as_float(0x7f800000);
    const float pen0   = (m0     < MM) ? pcm[c * MM + m0]     * (1.0f / (float)LL) : 0.0f;
    const float pen1   = (m0 + 1 < MM) ? pcm[c * MM + m0 + 1] * (1.0f / (float)LL) : 0.0f;
    const float guard0 = (m0     < MM) ? 0.0f : INF;
    const float guard1 = (m0 + 1 < MM) ? 0.0f : INF;

#pragma unroll
    for (int j = 0; j < NBLK; ++j) {
        // 4 independent chains per m; diff = FADD(neg), accum = FADD(|src|):
        // exactly 2 fma-pipe instructions per element, no marshalling.
        float s0a = 0.f, s0b = 0.f, s0c = 0.f, s0d = 0.f;   // m0
        float s1a = 0.f, s1b = 0.f, s1c = 0.f, s1d = 0.f;   // m0+1
#pragma unroll
        for (int k = 0; k < 6; ++k) {
            const float4 wv = wsm[j][k];                    // w[l], l = 4k..4k+3
            s0a += fabsf(xw[4 * k]     - wv.x);
            s0b += fabsf(xw[4 * k + 1] - wv.y);
            s0c += fabsf(xw[4 * k + 2] - wv.z);
            s0d += fabsf(xw[4 * k + 3] - wv.w);
            s1a += fabsf(xw[4 * k + 2] - wv.x);
            s1b += fabsf(xw[4 * k + 3] - wv.y);
            s1c += fabsf(xw[4 * k + 4] - wv.z);
            s1d += fabsf(xw[4 * k + 5] - wv.w);
        }
        const float s0 = (s0a + s0b) + (s0c + s0d);
        const float s1 = (s1a + s1b) + (s1c + s1d);
        const float d0 = fmaf(s0, pen0, guard0);
        const float d1 = fmaf(s1, pen1, guard1);
        dsm[j][tid] = make_float2(fminf(d0, d1),
                                  fminf(fabsf(d0), fabsf(d1)));
    }
    __syncthreads();

    // ---- 4 warps reduce 4 rows (warp w -> row w) ----
    {
        const int r = warp;
        float mn = INF, mna = INF;
#pragma unroll
        for (int i = 0; i < 4; ++i) {
            const float2 v = dsm[r][lane + i * 32];
            mn  = fminf(mn,  v.x);
            mna = fminf(mna, v.y);
        }
#pragma unroll
        for (int off = 16; off; off >>= 1) {
            mn  = fminf(mn,  __shfl_xor_sync(0xffffffffu, mn,  off));
            mna = fminf(mna, __shfl_xor_sync(0xffffffffu, mna, off));
        }
        if (lane == 0) {
            const int n = n0 + r;
            const int o = (b * NN + n) * CC + c;
            out[o] = expf(-(mna * mna));
            out[BB * NN * CC + o] = mn;
        }
    }
}

extern "C" void kernel_launch(void* const* d_in, const int* in_sizes, int n_in,
                              void* d_out, int out_size)
{
    const float* x   = (const float*)d_in[0];   // (B, C, T)
    const float* w   = (const float*)d_in[1];   // (N, C, L)
    const float* pcm = (const float*)d_in[2];   // (C, M)
    float* out = (float*)d_out;

    dim3 grid(BB * CC, NN / NBLK);              // 128 x 16 = 2048 blocks of 128 thr
    shapelet_kernel<<<grid, 128>>>(x, w, pcm, out);
}

// round 10
// speedup vs baseline: 1.1837x; 1.1837x over previous
#include <cuda_runtime.h>
#include <math.h>

// Shapelet_66932770341112 on sm_103a
// B=16, C=8, T=512, L=24, STRIDE=2, N=64, M=245, EPS=1
// d(b,m,n,c) = (1/L) * sum_l |x[b,c,2m+l] - w[n,c,l]| * pcm[c,m]
// out[0 : B*N*C]       = exp(-(min_m |d|)^2)
// out[B*N*C : 2*B*N*C] = min_m d

#define BB 16
#define CC 8
#define TT 512
#define LL 24
#define NN 64
#define MM 245
#define NBLK 8             // n per block

typedef unsigned long long ull;

__device__ __forceinline__ ull add_f32x2(ull a, ull b) {
    ull r;
    asm("add.rn.f32x2 %0, %1, %2;" : "=l"(r) : "l"(a), "l"(b));
    return r;
}
__device__ __forceinline__ float lo32(ull v) { return __int_as_float((unsigned)(v & 0xffffffffULL)); }
__device__ __forceinline__ float hi32(ull v) { return __int_as_float((unsigned)(v >> 32)); }

__global__ __launch_bounds__(256, 5)
void shapelet_kernel(const float* __restrict__ x,
                     const float* __restrict__ w,
                     const float* __restrict__ pcm,
                     float* __restrict__ out)
{
    // x pairs: pair(t) = (x[2t], x[2t+1]); 1 m per thread -> lane stride is
    // 1 pair (8B), naturally conflict-free, no swizzle needed.
    __shared__ ull   xsm[268];             // 256 pairs + 12 zero pad
    __shared__ ull   wneg[NBLK][12];       // 8 shapelets, negated, as pairs
    __shared__ float dsm[NBLK][256];       // d(m) per local n

    const int bc   = blockIdx.x;           // b*C + c
    const int b    = bc >> 3;
    const int c    = bc & 7;
    const int n0   = blockIdx.y * NBLK;
    const int tid  = threadIdx.x;           // == m
    const int lane = tid & 31;
    const int warp = tid >> 5;              // 0..7

    // ---- x row: 256 pairs + zero pad ----
    ((float2*)xsm)[tid] = ((const float2*)(x + bc * TT))[tid];
    if (tid < 12) ((float2*)xsm)[256 + tid] = make_float2(0.f, 0.f);

    // ---- 8 shapelets' weights for channel c, negated (192 floats) ----
    if (tid < NBLK * LL) {
        const int j = tid / LL;
        const int l = tid % LL;
        ((float*)wneg)[j * LL + l] = -w[((n0 + j) * CC + c) * LL + l];
    }
    __syncthreads();

    // ---- register window: xw[k] = pair(m + k), k=0..11 ----
    const int m = tid;
    ull xw[12];
#pragma unroll
    for (int k = 0; k < 12; ++k) xw[k] = xsm[m + k];

    const float INF   = __int_as_float(0x7f800000);
    const float pen   = (m < MM) ? pcm[c * MM + m] * (1.0f / (float)LL) : 0.0f;
    const float guard = (m < MM) ? 0.0f : INF;

#pragma unroll
    for (int j = 0; j < NBLK; ++j) {
        const ulonglong2* wp = (const ulonglong2*)wneg[j];
        // packed diff (FADD2) + scalar |src| accumulate (FADD): 1.5 instr/elem
        float a0 = 0.f, a1 = 0.f, a2 = 0.f, a3 = 0.f;   // 4 independent chains
#pragma unroll
        for (int k = 0; k < 6; ++k) {
            const ulonglong2 wv = wp[k];                 // weight pairs 2k, 2k+1
            const ull t0 = add_f32x2(xw[2 * k],     wv.x);
            const ull t1 = add_f32x2(xw[2 * k + 1], wv.y);
            a0 += fabsf(lo32(t0));  a1 += fabsf(hi32(t0));
            a2 += fabsf(lo32(t1));  a3 += fabsf(hi32(t1));
        }
        const float s = (a0 + a1) + (a2 + a3);
        dsm[j][m] = fmaf(s, pen, guard);
    }
    __syncthreads();

    // ---- 8 warps: warp w reduces row w over 256 m values ----
    {
        const float* row = dsm[warp];
        float mn = INF, mna = INF;
#pragma unroll
        for (int i = 0; i < 8; ++i) {
            const float v = row[lane + i * 32];
            mn  = fminf(mn,  v);
            mna = fminf(mna, fabsf(v));    // |src| modifier on FMNMX: free
        }
#pragma unroll
        for (int off = 16; off; off >>= 1) {
            mn  = fminf(mn,  __shfl_xor_sync(0xffffffffu, mn,  off));
            mna = fminf(mna, __shfl_xor_sync(0xffffffffu, mna, off));
        }
        if (lane == 0) {
            const int n = n0 + warp;
            const int o = (b * NN + n) * CC + c;
            out[o] = expf(-(mna * mna));
            out[BB * NN * CC + o] = mn;
        }
    }
}

extern "C" void kernel_launch(void* const* d_in, const int* in_sizes, int n_in,
                              void* d_out, int out_size)
{
    const float* x   = (const float*)d_in[0];   // (B, C, T)
    const float* w   = (const float*)d_in[1];   // (N, C, L)
    const float* pcm = (const float*)d_in[2];   // (C, M)
    float* out = (float*)d_out;

    dim3 grid(BB * CC, NN / NBLK);              // 128 x 8 = 1024 blocks of 256 thr
    shapelet_kernel<<<grid, 256>>>(x, w, pcm, out);
}

// round 11
// speedup vs baseline: 1.2156x; 1.0269x over previous
#include <cuda_runtime.h>
#include <math.h>

// Shapelet_66932770341112 on sm_103a
// B=16, C=8, T=512, L=24, STRIDE=2, N=64, M=245, EPS=1
// d(b,m,n,c) = (1/L) * sum_l |x[b,c,2m+l] - w[n,c,l]| * pcm[c,m]
// out[0 : B*N*C]       = exp(-(min_m |d|)^2)
// out[B*N*C : 2*B*N*C] = min_m d

#define BB 16
#define CC 8
#define TT 512
#define LL 24
#define NN 64
#define MM 245
#define NBLK 8             // n per block (processed as 4 pairs)

typedef unsigned long long ull;

__device__ __forceinline__ ull add_f32x2(ull a, ull b) {
    ull r;
    asm("add.rn.f32x2 %0, %1, %2;" : "=l"(r) : "l"(a), "l"(b));
    return r;
}
__device__ __forceinline__ float lo32(ull v) { return __int_as_float((unsigned)(v & 0xffffffffULL)); }
__device__ __forceinline__ float hi32(ull v) { return __int_as_float((unsigned)(v >> 32)); }

__global__ __launch_bounds__(256, 4)
void shapelet_kernel(const float* __restrict__ x,
                     const float* __restrict__ w,
                     const float* __restrict__ pcm,
                     float* __restrict__ out)
{
    __shared__ ull   xsm[268];             // x pairs: pair(t)=(x[2t],x[2t+1]) + pad
    __shared__ ull   wneg[NBLK][12];       // 8 shapelets, negated, as pairs
    __shared__ float dsm[NBLK][256];       // d(m) per local n

    const int bc   = blockIdx.x;           // b*C + c
    const int b    = bc >> 3;
    const int c    = bc & 7;
    const int n0   = blockIdx.y * NBLK;
    const int tid  = threadIdx.x;           // == m
    const int lane = tid & 31;
    const int warp = tid >> 5;              // 0..7

    ((float2*)xsm)[tid] = ((const float2*)(x + bc * TT))[tid];
    if (tid < 12) ((float2*)xsm)[256 + tid] = make_float2(0.f, 0.f);

    if (tid < NBLK * LL) {
        const int j = tid / LL;
        const int l = tid % LL;
        ((float*)wneg)[j * LL + l] = -w[((n0 + j) * CC + c) * LL + l];
    }
    __syncthreads();

    // ---- register window: xw[k] = pair(m + k), k=0..11 ----
    const int m = tid;
    ull xw[12];
#pragma unroll
    for (int k = 0; k < 12; ++k) xw[k] = xsm[m + k];

    const float INF   = __int_as_float(0x7f800000);
    const float pen   = (m < MM) ? pcm[c * MM + m] * (1.0f / (float)LL) : 0.0f;
    const float guard = (m < MM) ? 0.0f : INF;

    // ---- 4 iterations, each processing TWO shapelets with independent chains ----
#pragma unroll
    for (int jp = 0; jp < NBLK / 2; ++jp) {
        const ulonglong2* wp0 = (const ulonglong2*)wneg[2 * jp];
        const ulonglong2* wp1 = (const ulonglong2*)wneg[2 * jp + 1];
        float a0 = 0.f, a1 = 0.f, a2 = 0.f, a3 = 0.f;   // shapelet 2*jp
        float b0 = 0.f, b1 = 0.f, b2 = 0.f, b3 = 0.f;   // shapelet 2*jp+1
#pragma unroll
        for (int k = 0; k < 6; ++k) {
            const ulonglong2 wv0 = wp0[k];
            const ulonglong2 wv1 = wp1[k];
            const ull t0 = add_f32x2(xw[2 * k],     wv0.x);
            const ull t1 = add_f32x2(xw[2 * k + 1], wv0.y);
            const ull u0 = add_f32x2(xw[2 * k],     wv1.x);
            const ull u1 = add_f32x2(xw[2 * k + 1], wv1.y);
            a0 += fabsf(lo32(t0));  a1 += fabsf(hi32(t0));
            a2 += fabsf(lo32(t1));  a3 += fabsf(hi32(t1));
            b0 += fabsf(lo32(u0));  b1 += fabsf(hi32(u0));
            b2 += fabsf(lo32(u1));  b3 += fabsf(hi32(u1));
        }
        const float s0 = (a0 + a1) + (a2 + a3);
        const float s1 = (b0 + b1) + (b2 + b3);
        dsm[2 * jp][m]     = fmaf(s0, pen, guard);
        dsm[2 * jp + 1][m] = fmaf(s1, pen, guard);
    }
    __syncthreads();

    // ---- 8 warps: warp w reduces row w over 256 m values ----
    {
        const float* row = dsm[warp];
        float mn = INF, mna = INF;
#pragma unroll
        for (int i = 0; i < 8; ++i) {
            const float v = row[lane + i * 32];
            mn  = fminf(mn,  v);
            mna = fminf(mna, fabsf(v));
        }
#pragma unroll
        for (int off = 16; off; off >>= 1) {
            mn  = fminf(mn,  __shfl_xor_sync(0xffffffffu, mn,  off));
            mna = fminf(mna, __shfl_xor_sync(0xffffffffu, mna, off));
        }
        if (lane == 0) {
            const int n = n0 + warp;
            const int o = (b * NN + n) * CC + c;
            out[o] = expf(-(mna * mna));
            out[BB * NN * CC + o] = mn;
        }
    }
}

extern "C" void kernel_launch(void* const* d_in, const int* in_sizes, int n_in,
                              void* d_out, int out_size)
{
    const float* x   = (const float*)d_in[0];   // (B, C, T)
    const float* w   = (const float*)d_in[1];   // (N, C, L)
    const float* pcm = (const float*)d_in[2];   // (C, M)
    float* out = (float*)d_out;

    dim3 grid(BB * CC, NN / NBLK);              // 128 x 8 = 1024 blocks of 256 thr
    shapelet_kernel<<<grid, 256>>>(x, w, pcm, out);
}